// round 2
// baseline (speedup 1.0000x reference)
#include <cuda_runtime.h>
#include <cuda_bf16.h>
#include <cstdint>

// out[v, t, n] = tlut[encoded[t, n], v]
// tlut:   (65536, 2) float32  -> each row is a contiguous float2 (8B)
// encoded:(128, 262144) int32
// out:    (2, 128, 262144) float32
//
// L1-wavefront-bound gather. Policy tuning:
//  - enc loads:  ld.global.cg  (L2-only, don't thrash L1 with stream data)
//  - LUT gathers: ld.global.nc.L1::evict_last  (pin the 512KB table in L1)
//  - stores:     st.global.cs  (evict-first streaming)
// 2 quads per thread for ILP through miss latency.

static constexpr long long TB_ = 128;
static constexpr long long N_  = 262144;
static constexpr long long TOTAL  = TB_ * N_;      // 33,554,432 per plane
static constexpr long long TOTAL4 = TOTAL / 4;     // 8,388,608 quads
static constexpr int QUADS_PER_THREAD = 2;

__device__ __forceinline__ int4 ldcg_int4(const int4* p) {
    int4 v;
    asm volatile("ld.global.cg.v4.s32 {%0,%1,%2,%3}, [%4];"
                 : "=r"(v.x), "=r"(v.y), "=r"(v.z), "=r"(v.w) : "l"(p));
    return v;
}

__device__ __forceinline__ float2 ld_lut(const float2* p) {
    float2 v;
    asm volatile("ld.global.nc.L1::evict_last.v2.f32 {%0,%1}, [%2];"
                 : "=f"(v.x), "=f"(v.y) : "l"(p));
    return v;
}

__device__ __forceinline__ void stcs_float4(float4* p, float4 v) {
    asm volatile("st.global.cs.v4.f32 [%0], {%1,%2,%3,%4};"
                 :: "l"(p), "f"(v.x), "f"(v.y), "f"(v.z), "f"(v.w));
}

__global__ void __launch_bounds__(256, 8)
bitshift_lut_gather_kernel(const float2* __restrict__ lut,
                           const int4*  __restrict__ enc,
                           float4* __restrict__ out0,
                           float4* __restrict__ out1)
{
    // Each block handles 256*QUADS_PER_THREAD consecutive quads,
    // thread t gets quads (base + t) and (base + t + 256): coalesced per access.
    long long base = (long long)blockIdx.x * (256 * QUADS_PER_THREAD) + threadIdx.x;

    int4 e0 = ldcg_int4(&enc[base]);
    int4 e1 = ldcg_int4(&enc[base + 256]);

    // 8 independent gathers in flight
    float2 a0 = ld_lut(&lut[e0.x]);
    float2 b0 = ld_lut(&lut[e0.y]);
    float2 c0 = ld_lut(&lut[e0.z]);
    float2 d0 = ld_lut(&lut[e0.w]);
    float2 a1 = ld_lut(&lut[e1.x]);
    float2 b1 = ld_lut(&lut[e1.y]);
    float2 c1 = ld_lut(&lut[e1.z]);
    float2 d1 = ld_lut(&lut[e1.w]);

    stcs_float4(&out0[base],        make_float4(a0.x, b0.x, c0.x, d0.x));
    stcs_float4(&out1[base],        make_float4(a0.y, b0.y, c0.y, d0.y));
    stcs_float4(&out0[base + 256],  make_float4(a1.x, b1.x, c1.x, d1.x));
    stcs_float4(&out1[base + 256],  make_float4(a1.y, b1.y, c1.y, d1.y));
}

extern "C" void kernel_launch(void* const* d_in, const int* in_sizes, int n_in,
                              void* d_out, int out_size)
{
    const float2* lut = (const float2*)d_in[0];   // tlut (65536, 2)
    const int4*   enc = (const int4*)d_in[1];     // encoded (128, 262144)
    float* out = (float*)d_out;                   // (2, 128, 262144)

    float4* out0 = (float4*)out;
    float4* out1 = (float4*)(out + TOTAL);

    const int threads = 256;
    const long long quads_per_block = threads * QUADS_PER_THREAD;
    const int blocks = (int)(TOTAL4 / quads_per_block);   // 16384, divides exactly
    bitshift_lut_gather_kernel<<<blocks, threads>>>(lut, enc, out0, out1);
}